// round 15
// baseline (speedup 1.0000x reference)
#include <cuda_runtime.h>
#include <cuda_fp16.h>
#include <math.h>
#include <stdint.h>

#define HDIM 2048
#define NEXP 16
#define TOPK 4
#define IDIM 1408
#define ISDIM 5632
#define TMAX 8192
#define TKMAX (TMAX * TOPK)

typedef unsigned short u16;
typedef unsigned int u32;

// ---------------------------------------------------------------------------
// Device scratch (static device globals; no allocations anywhere)
// ---------------------------------------------------------------------------
#define WEXP ((size_t)NEXP * HDIM * IDIM)   // 46,137,344
#define WSH ((size_t)HDIM * ISDIM)          // 11,534,336
#define HELEMS ((size_t)46137344)           // == T*Is == T*K*I

__device__ u16 g_wu[2 * WEXP];              // interleaved w1/w3 fp16 [E,2I,H]
__device__ u16 g_w2h[WEXP];                 // w2 fp16 transposed [E,H,I]
__device__ u16 g_su[2 * WSH];               // interleaved sw1/sw3 [2Is,H]
__device__ u16 g_s2h[WSH];                  // sw2 fp16 transposed [H,Is]
__device__ u16 g_xh[(size_t)TMAX * HDIM];   // x single fp16
__device__ u16 g_hh[HELEMS];                // h single fp16
__device__ float g_dtmp[(size_t)TKMAX * HDIM];  // routed down rows (compact)
__device__ int g_topi[TKMAX], g_btok[TKMAX], g_posmap[TKMAX];
__device__ float g_topw[TKMAX], g_gate[TMAX];
__device__ int g_counts[NEXP], g_offsets[NEXP], g_cursor[NEXP];

// ---------------------------------------------------------------------------
// PTX helpers
// ---------------------------------------------------------------------------
__device__ __forceinline__ u32 s2u(const void* p) {
    u32 a;
    asm("{ .reg .u64 t; cvta.to.shared.u64 t, %1; cvt.u32.u64 %0, t; }"
        : "=r"(a) : "l"(p));
    return a;
}
__device__ __forceinline__ void cp16(u32 d, const void* s) {
    asm volatile("cp.async.cg.shared.global [%0], [%1], 16;"
                 :: "r"(d), "l"(s) : "memory");
}
__device__ __forceinline__ void ldsm_x4(u32 a, u32& r0, u32& r1, u32& r2, u32& r3) {
    asm volatile("ldmatrix.sync.aligned.m8n8.x4.shared.b16 {%0,%1,%2,%3}, [%4];"
                 : "=r"(r0), "=r"(r1), "=r"(r2), "=r"(r3) : "r"(a));
}
__device__ __forceinline__ void mma16816(float* c, u32 a0, u32 a1, u32 a2, u32 a3,
                                         u32 b0, u32 b1) {
    asm volatile(
        "mma.sync.aligned.m16n8k16.row.col.f32.f16.f16.f32 "
        "{%0,%1,%2,%3}, {%4,%5,%6,%7}, {%8,%9}, {%0,%1,%2,%3};"
        : "+f"(c[0]), "+f"(c[1]), "+f"(c[2]), "+f"(c[3])
        : "r"(a0), "r"(a1), "r"(a2), "r"(a3), "r"(b0), "r"(b1));
}

// ---------------------------------------------------------------------------
// Router + bucketing
// ---------------------------------------------------------------------------
__global__ void router_k(const float* __restrict__ x, const float* __restrict__ gw,
                         const float* __restrict__ sgw,
                         int* __restrict__ topi, float* __restrict__ topw,
                         float* __restrict__ gatev, int* __restrict__ counts) {
    int t = blockIdx.x;
    const float* xr = x + (size_t)t * HDIM;
    float acc[17];
#pragma unroll
    for (int e = 0; e < 17; e++) acc[e] = 0.f;
    for (int h = threadIdx.x; h < HDIM; h += blockDim.x) {
        float xv = xr[h];
        const float* g = gw + h * NEXP;
#pragma unroll
        for (int e = 0; e < NEXP; e++) acc[e] += xv * g[e];
        acc[16] += xv * sgw[h];
    }
    __shared__ float red[17][8];
    int lane = threadIdx.x & 31, w = threadIdx.x >> 5;
#pragma unroll
    for (int e = 0; e < 17; e++) {
        float v = acc[e];
#pragma unroll
        for (int o = 16; o; o >>= 1) v += __shfl_down_sync(0xffffffffu, v, o);
        if (lane == 0) red[e][w] = v;
    }
    __syncthreads();
    if (threadIdx.x == 0) {
        float l[17];
#pragma unroll
        for (int e = 0; e < 17; e++) {
            float s = 0.f;
#pragma unroll
            for (int i = 0; i < 8; i++) s += red[e][i];
            l[e] = s;
        }
        float mx = l[0];
#pragma unroll
        for (int e = 1; e < NEXP; e++) mx = fmaxf(mx, l[e]);
        float p[NEXP], sum = 0.f;
#pragma unroll
        for (int e = 0; e < NEXP; e++) { p[e] = expf(l[e] - mx); sum += p[e]; }
        float inv = 1.f / sum;
        bool used[NEXP];
#pragma unroll
        for (int e = 0; e < NEXP; e++) used[e] = false;
        for (int k = 0; k < TOPK; k++) {
            int best = 0; float bv = -1.f;
#pragma unroll
            for (int e = 0; e < NEXP; e++)
                if (!used[e] && p[e] > bv) { bv = p[e]; best = e; }
            used[best] = true;
            topi[t * TOPK + k] = best;
            topw[t * TOPK + k] = bv * inv;
            atomicAdd(&counts[best], 1);
        }
        gatev[t] = 1.f / (1.f + expf(-l[16]));
    }
}

__global__ void zero_counts_k(int* __restrict__ c) {
    if (threadIdx.x < NEXP) c[threadIdx.x] = 0;
}
__global__ void prefix_k(const int* __restrict__ c, int* __restrict__ off,
                         int* __restrict__ cur) {
    if (threadIdx.x == 0) {
        int s = 0;
        for (int e = 0; e < NEXP; e++) { off[e] = s; cur[e] = s; s += c[e]; }
    }
}
__global__ void scatter_k(const int* __restrict__ topi, int* __restrict__ cur,
                          int* __restrict__ btok, int* __restrict__ posmap, int TK) {
    int i = blockIdx.x * blockDim.x + threadIdx.x;
    if (i < TK) {
        int pos = atomicAdd(&cur[topi[i]], 1);
        btok[pos] = i >> 2;
        posmap[i] = pos;
    }
}

// ---------------------------------------------------------------------------
// Prep kernels
// ---------------------------------------------------------------------------
__global__ void cvtx_k(const float* __restrict__ x, u16* __restrict__ xh, size_t n) {
    size_t i = (size_t)blockIdx.x * blockDim.x + threadIdx.x;
    if (i < n) xh[i] = __half_as_ushort(__float2half_rn(x[i]));
}

// transpose [K,N] -> [N,K] fp16
__global__ void tsplit1_k(const float* __restrict__ in, u16* __restrict__ oh,
                          int K, int N) {
    __shared__ float t[32][33];
    size_t eo = (size_t)blockIdx.z * K * N;
    int n0 = blockIdx.x * 32, k0 = blockIdx.y * 32;
    for (int i = threadIdx.y; i < 32; i += 8)
        t[i][threadIdx.x] = in[eo + (size_t)(k0 + i) * N + n0 + threadIdx.x];
    __syncthreads();
    for (int i = threadIdx.y; i < 32; i += 8) {
        float v = t[threadIdx.x][i];
        oh[eo + (size_t)(n0 + i) * K + k0 + threadIdx.x] =
            __half_as_ushort(__float2half_rn(v));
    }
}

// transpose + interleave: source col n -> out row (n/8)*16 + sel*8 + n%8
__global__ void tinter_k(const float* __restrict__ in, u16* __restrict__ out,
                         int K, int N, int sel) {
    __shared__ float t[32][33];
    size_t eoi = (size_t)blockIdx.z * K * N;
    size_t eoo = (size_t)blockIdx.z * 2 * K * N;
    int n0 = blockIdx.x * 32, k0 = blockIdx.y * 32;
    for (int i = threadIdx.y; i < 32; i += 8)
        t[i][threadIdx.x] = in[eoi + (size_t)(k0 + i) * N + n0 + threadIdx.x];
    __syncthreads();
    for (int i = threadIdx.y; i < 32; i += 8) {
        float v = t[threadIdx.x][i];
        int n = n0 + i;
        int orow = ((n >> 3) << 4) + sel * 8 + (n & 7);
        out[eoo + (size_t)orow * K + k0 + threadIdx.x] =
            __half_as_ushort(__float2half_rn(v));
    }
}

// ---------------------------------------------------------------------------
// Single-term fp16 HMMA GEMM, 256x128 CTA tile, BK=32, 2 stages, 256 threads,
// 128x32 warp tiles (8 warps, 2x4). Per-kk batched ldsm (fits registers).
//   MODE 0: fused up-proj, B interleaved [w1|w3]; epilogue h=silu(g)*u -> Hh
//   MODE 1: down dense:  Fout[m*N+n] = gate[m]*acc
//   MODE 2: down routed: Fout[(off+m)*N+n] = acc  (A rows compact at off)
// ROUTED (MODE 0): A rows gathered via btok.
// ---------------------------------------------------------------------------
#define ATILE_B 20480           // 256 rows * 80B (64B data + 16B pad)
#define BTILE_B 10240           // 128 rows * 80B
#define STAGE_B2 (ATILE_B + BTILE_B)  // 30,720
#define SMEM_G (2 * STAGE_B2)         // 61,440

template <int MODE, bool ROUTED>
__global__ void __launch_bounds__(256)
hmma_k(const u16* __restrict__ Ah, const u16* __restrict__ Bh,
       u16* __restrict__ Hh, float* __restrict__ Fout,
       const float* __restrict__ gate,
       const int* __restrict__ counts, const int* __restrict__ offsets,
       const int* __restrict__ btok, int M, int N, int Kd) {
    int Ne = M, off = 0;
    if (ROUTED) {
        int e = blockIdx.z;
        Ne = counts[e];
        off = offsets[e];
        Bh += (size_t)e * N * Kd;
    }
    int rowblock = blockIdx.y * 256;
    if (rowblock >= Ne) return;
    int colblock = blockIdx.x * 128;
    int Nlog = N >> 1;   // MODE 0 only

    extern __shared__ char dynsm[];
    u32 sbase = s2u(dynsm);

    int tid = threadIdx.x;
    int lane = tid & 31, wid = tid >> 5;
    int wm = wid >> 2, wn = wid & 3;   // warp tile: rows wm*128, cols wn*32

    // ---- loader: 6 x 16B cp.async per thread per chunk (A 1024 + B 512) ----
    const char* gptr[6];
    u32 soff[6];
#pragma unroll
    for (int j = 0; j < 6; j++) {
        int i = tid + 256 * j;
        const u16* bp;
        if (i < 1024) {            // A tile: 256 rows x 4 chunks
            int row = i >> 2, cc = i & 3;
            soff[j] = row * 80 + cc * 16;
            int m = rowblock + row;
            int mc = (m < Ne) ? m : (Ne - 1);
            size_t gr;
            if (ROUTED) gr = (MODE == 0) ? (size_t)btok[off + mc] : (size_t)(off + mc);
            else gr = (size_t)mc;
            bp = Ah + gr * Kd;
            gptr[j] = (const char*)bp + cc * 16;
        } else {                   // B tile: 128 rows x 4 chunks
            int idx = i - 1024;
            int row = idx >> 2, cc = idx & 3;
            soff[j] = ATILE_B + row * 80 + cc * 16;
            bp = Bh + (size_t)(colblock + row) * Kd;
            gptr[j] = (const char*)bp + cc * 16;
        }
    }

    const int NC = Kd >> 5;  // BK = 32

    auto load_chunk = [&](int c, int s) {
        u32 stg = sbase + s * STAGE_B2;
        int kb = c * 64;
#pragma unroll
        for (int j = 0; j < 6; j++) cp16(stg + soff[j], gptr[j] + kb);
        asm volatile("cp.async.commit_group;" ::: "memory");
    };

    float acc[8][4][4];
#pragma unroll
    for (int a = 0; a < 8; a++)
#pragma unroll
        for (int b = 0; b < 4; b++)
#pragma unroll
            for (int d = 0; d < 4; d++) acc[a][b][d] = 0.f;

    u32 aoff = (u32)(((lane & 7) + ((lane >> 3) & 1) * 8) * 80 + ((lane >> 4) & 1) * 16);
    u32 boff = (u32)(((lane & 7) + ((lane >> 4) & 1) * 8) * 80 + ((lane >> 3) & 1) * 16);

    load_chunk(0, 0);
    load_chunk(1, 1);

    for (int c = 0; c < NC; c++) {
        int s = c & 1;
        if (c + 1 < NC) asm volatile("cp.async.wait_group 1;" ::: "memory");
        else            asm volatile("cp.async.wait_group 0;" ::: "memory");
        __syncthreads();

        u32 ab = sbase + s * STAGE_B2;

#pragma unroll
        for (int kk = 0; kk < 2; kk++) {
            u32 ah[8][4], bh[4][2];
#pragma unroll
            for (int mt = 0; mt < 8; mt++) {
                u32 addr = ab + (u32)((wm * 128 + mt * 16) * 80) + aoff + kk * 32;
                ldsm_x4(addr, ah[mt][0], ah[mt][1], ah[mt][2], ah[mt][3]);
            }
            {
                u32 bb = ab + ATILE_B + (u32)(wn * 32 * 80) + boff + kk * 32;
                ldsm_x4(bb,           bh[0][0], bh[0][1], bh[1][0], bh[1][1]);
                ldsm_x4(bb + 16 * 80, bh[2][0], bh[2][1], bh[3][0], bh[3][1]);
            }
#pragma unroll
            for (int mt = 0; mt < 8; mt++)
#pragma unroll
                for (int nt = 0; nt < 4; nt++)
                    mma16816(acc[mt][nt], ah[mt][0], ah[mt][1],
                             ah[mt][2], ah[mt][3],
                             bh[nt][0], bh[nt][1]);
        }

        __syncthreads();
        if (c + 2 < NC) load_chunk(c + 2, s);
    }

    // ---- epilogue ----
    int g = lane >> 2, q = lane & 3;
#pragma unroll
    for (int mt = 0; mt < 8; mt++) {
#pragma unroll
        for (int h2 = 0; h2 < 2; h2++) {
            int m = rowblock + wm * 128 + mt * 16 + g + 8 * h2;
            if (m >= Ne) continue;
            size_t orow = (size_t)((ROUTED ? off : 0) + m);
            if (MODE == 0) {
#pragma unroll
                for (int j = 0; j < 2; j++) {
                    float g0 = acc[mt][2 * j][2 * h2 + 0];
                    float g1 = acc[mt][2 * j][2 * h2 + 1];
                    float u0 = acc[mt][2 * j + 1][2 * h2 + 0];
                    float u1 = acc[mt][2 * j + 1][2 * h2 + 1];
                    float h0 = (g0 / (1.f + expf(-g0))) * u0;
                    float h1 = (g1 / (1.f + expf(-g1))) * u1;
                    int nlog = (colblock >> 1) + wn * 16 + j * 8 + 2 * q;
                    *(u32*)&Hh[orow * Nlog + nlog] =
                        (u32)__half_as_ushort(__float2half_rn(h0)) |
                        ((u32)__half_as_ushort(__float2half_rn(h1)) << 16);
                }
            } else {
                float gsc = (MODE == 1) ? gate[m] : 1.f;
#pragma unroll
                for (int nt = 0; nt < 4; nt++) {
                    int n = colblock + wn * 32 + nt * 8 + 2 * q;
                    float v0 = gsc * acc[mt][nt][2 * h2 + 0];
                    float v1 = gsc * acc[mt][nt][2 * h2 + 1];
                    *(float2*)&Fout[orow * N + n] = make_float2(v0, v1);
                }
            }
        }
    }
}

// ---------------------------------------------------------------------------
// Combine: out[t,:] += sum_k topw[t,k] * dtmp[posmap[t,k],:]
// ---------------------------------------------------------------------------
__global__ void combine_k(float* __restrict__ out, const float* __restrict__ dtmp,
                          const int* __restrict__ posmap, const float* __restrict__ topw,
                          int T) {
    int idx = blockIdx.x * blockDim.x + threadIdx.x;
    int HV = HDIM / 4;
    if (idx >= T * HV) return;
    int t = idx / HV, hv = idx % HV;
    float4 o = ((const float4*)out)[idx];
#pragma unroll
    for (int k = 0; k < TOPK; k++) {
        int p = posmap[t * TOPK + k];
        float w = topw[t * TOPK + k];
        float4 d = ((const float4*)dtmp)[(size_t)p * HV + hv];
        o.x += w * d.x; o.y += w * d.y; o.z += w * d.z; o.w += w * d.w;
    }
    ((float4*)out)[idx] = o;
}

// ---------------------------------------------------------------------------
// kernel_launch
// ---------------------------------------------------------------------------
extern "C" void kernel_launch(void* const* d_in, const int* in_sizes, int n_in,
                              void* d_out, int out_size) {
    const float* x   = (const float*)d_in[0];
    const float* gw  = (const float*)d_in[1];
    const float* w1  = (const float*)d_in[2];
    const float* w3  = (const float*)d_in[3];
    const float* w2  = (const float*)d_in[4];
    const float* sw1 = (const float*)d_in[5];
    const float* sw3 = (const float*)d_in[6];
    const float* sw2 = (const float*)d_in[7];
    const float* sgw = (const float*)d_in[8];
    float* out = (float*)d_out;

    const int T = in_sizes[0] / HDIM;   // 8192
    const int TK = T * TOPK;

    u16 *wu, *w2h, *su, *s2h, *xh, *hh;
    float *dtmp, *topw, *gatev;
    int *topi, *counts, *offsets, *cursor, *btok, *posmap;
    cudaGetSymbolAddress((void**)&wu, g_wu);
    cudaGetSymbolAddress((void**)&w2h, g_w2h);
    cudaGetSymbolAddress((void**)&su, g_su);
    cudaGetSymbolAddress((void**)&s2h, g_s2h);
    cudaGetSymbolAddress((void**)&xh, g_xh);
    cudaGetSymbolAddress((void**)&hh, g_hh);
    cudaGetSymbolAddress((void**)&dtmp, g_dtmp);
    cudaGetSymbolAddress((void**)&topi, g_topi);
    cudaGetSymbolAddress((void**)&topw, g_topw);
    cudaGetSymbolAddress((void**)&gatev, g_gate);
    cudaGetSymbolAddress((void**)&counts, g_counts);
    cudaGetSymbolAddress((void**)&offsets, g_offsets);
    cudaGetSymbolAddress((void**)&cursor, g_cursor);
    cudaGetSymbolAddress((void**)&btok, g_btok);
    cudaGetSymbolAddress((void**)&posmap, g_posmap);

    cudaFuncSetAttribute(hmma_k<0, false>, cudaFuncAttributeMaxDynamicSharedMemorySize, SMEM_G);
    cudaFuncSetAttribute(hmma_k<0, true>,  cudaFuncAttributeMaxDynamicSharedMemorySize, SMEM_G);
    cudaFuncSetAttribute(hmma_k<1, false>, cudaFuncAttributeMaxDynamicSharedMemorySize, SMEM_G);
    cudaFuncSetAttribute(hmma_k<2, true>,  cudaFuncAttributeMaxDynamicSharedMemorySize, SMEM_G);

    // ---- routing ----
    zero_counts_k<<<1, 32>>>(counts);
    router_k<<<T, 256>>>(x, gw, sgw, topi, topw, gatev, counts);
    prefix_k<<<1, 32>>>(counts, offsets, cursor);
    scatter_k<<<(TK + 255) / 256, 256>>>(topi, cursor, btok, posmap, TK);

    // ---- prep ----
    {
        size_t n = (size_t)T * HDIM;
        cvtx_k<<<(int)((n + 255) / 256), 256>>>(x, xh, n);
        dim3 b(32, 8);
        tinter_k<<<dim3(IDIM / 32, HDIM / 32, NEXP), b>>>(w1, wu, HDIM, IDIM, 0);
        tinter_k<<<dim3(IDIM / 32, HDIM / 32, NEXP), b>>>(w3, wu, HDIM, IDIM, 1);
        tsplit1_k<<<dim3(HDIM / 32, IDIM / 32, NEXP), b>>>(w2, w2h, IDIM, HDIM);
        tinter_k<<<dim3(ISDIM / 32, HDIM / 32, 1), b>>>(sw1, su, HDIM, ISDIM, 0);
        tinter_k<<<dim3(ISDIM / 32, HDIM / 32, 1), b>>>(sw3, su, HDIM, ISDIM, 1);
        tsplit1_k<<<dim3(HDIM / 32, ISDIM / 32, 1), b>>>(sw2, s2h, ISDIM, HDIM);
    }

    // ---- shared expert ----
    hmma_k<0, false><<<dim3(2 * ISDIM / 128, T / 256), 256, SMEM_G>>>(
        xh, su, hh, nullptr, nullptr, nullptr, nullptr, nullptr,
        T, 2 * ISDIM, HDIM);
    hmma_k<1, false><<<dim3(HDIM / 128, T / 256), 256, SMEM_G>>>(
        hh, s2h, nullptr, out, gatev, nullptr, nullptr, nullptr,
        T, HDIM, ISDIM);

    // ---- routed experts ----
    hmma_k<0, true><<<dim3(2 * IDIM / 128, TK / 256, NEXP), 256, SMEM_G>>>(
        xh, wu, hh, nullptr, nullptr, counts, offsets, btok,
        TK, 2 * IDIM, HDIM);
    hmma_k<2, true><<<dim3(HDIM / 128, TK / 256, NEXP), 256, SMEM_G>>>(
        hh, w2h, nullptr, dtmp, nullptr, counts, offsets, nullptr,
        TK, HDIM, IDIM);

    // ---- combine ----
    combine_k<<<(T * (HDIM / 4) + 255) / 256, 256>>>(out, dtmp, posmap, topw, T);
}

// round 16
// speedup vs baseline: 1.2497x; 1.2497x over previous
#include <cuda_runtime.h>
#include <cuda_fp16.h>
#include <math.h>
#include <stdint.h>

#define HDIM 2048
#define NEXP 16
#define TOPK 4
#define IDIM 1408
#define ISDIM 5632
#define TMAX 8192
#define TKMAX (TMAX * TOPK)

typedef unsigned short u16;
typedef unsigned int u32;

// ---------------------------------------------------------------------------
// Device scratch (static device globals; no allocations anywhere)
// ---------------------------------------------------------------------------
#define WEXP ((size_t)NEXP * HDIM * IDIM)   // 46,137,344
#define WSH ((size_t)HDIM * ISDIM)          // 11,534,336
#define HELEMS ((size_t)46137344)           // == T*Is == T*K*I

__device__ u16 g_wu[2 * WEXP];              // interleaved w1/w3 fp16 [E,2I,H]
__device__ u16 g_w2h[WEXP];                 // w2 fp16 transposed [E,H,I]
__device__ u16 g_su[2 * WSH];               // interleaved sw1/sw3 [2Is,H]
__device__ u16 g_s2h[WSH];                  // sw2 fp16 transposed [H,Is]
__device__ u16 g_xh[(size_t)TMAX * HDIM];   // x single fp16
__device__ u16 g_hh[HELEMS];                // h single fp16
__device__ float g_dtmp[(size_t)TKMAX * HDIM];  // routed down rows (compact)
__device__ int g_topi[TKMAX], g_btok[TKMAX], g_posmap[TKMAX];
__device__ float g_topw[TKMAX], g_gate[TMAX];
__device__ int g_counts[NEXP], g_offsets[NEXP], g_cursor[NEXP];

// ---------------------------------------------------------------------------
// PTX helpers
// ---------------------------------------------------------------------------
__device__ __forceinline__ u32 s2u(const void* p) {
    u32 a;
    asm("{ .reg .u64 t; cvta.to.shared.u64 t, %1; cvt.u32.u64 %0, t; }"
        : "=r"(a) : "l"(p));
    return a;
}
__device__ __forceinline__ void cp16(u32 d, const void* s) {
    asm volatile("cp.async.cg.shared.global [%0], [%1], 16;"
                 :: "r"(d), "l"(s) : "memory");
}
__device__ __forceinline__ void ldsm_x4(u32 a, u32& r0, u32& r1, u32& r2, u32& r3) {
    asm volatile("ldmatrix.sync.aligned.m8n8.x4.shared.b16 {%0,%1,%2,%3}, [%4];"
                 : "=r"(r0), "=r"(r1), "=r"(r2), "=r"(r3) : "r"(a));
}
__device__ __forceinline__ void mma16816(float* c, u32 a0, u32 a1, u32 a2, u32 a3,
                                         u32 b0, u32 b1) {
    asm volatile(
        "mma.sync.aligned.m16n8k16.row.col.f32.f16.f16.f32 "
        "{%0,%1,%2,%3}, {%4,%5,%6,%7}, {%8,%9}, {%0,%1,%2,%3};"
        : "+f"(c[0]), "+f"(c[1]), "+f"(c[2]), "+f"(c[3])
        : "r"(a0), "r"(a1), "r"(a2), "r"(a3), "r"(b0), "r"(b1));
}

// ---------------------------------------------------------------------------
// Router + bucketing
// ---------------------------------------------------------------------------
__global__ void router_k(const float* __restrict__ x, const float* __restrict__ gw,
                         const float* __restrict__ sgw,
                         int* __restrict__ topi, float* __restrict__ topw,
                         float* __restrict__ gatev, int* __restrict__ counts) {
    int t = blockIdx.x;
    const float* xr = x + (size_t)t * HDIM;
    float acc[17];
#pragma unroll
    for (int e = 0; e < 17; e++) acc[e] = 0.f;
    for (int h = threadIdx.x; h < HDIM; h += blockDim.x) {
        float xv = xr[h];
        const float* g = gw + h * NEXP;
#pragma unroll
        for (int e = 0; e < NEXP; e++) acc[e] += xv * g[e];
        acc[16] += xv * sgw[h];
    }
    __shared__ float red[17][8];
    int lane = threadIdx.x & 31, w = threadIdx.x >> 5;
#pragma unroll
    for (int e = 0; e < 17; e++) {
        float v = acc[e];
#pragma unroll
        for (int o = 16; o; o >>= 1) v += __shfl_down_sync(0xffffffffu, v, o);
        if (lane == 0) red[e][w] = v;
    }
    __syncthreads();
    if (threadIdx.x == 0) {
        float l[17];
#pragma unroll
        for (int e = 0; e < 17; e++) {
            float s = 0.f;
#pragma unroll
            for (int i = 0; i < 8; i++) s += red[e][i];
            l[e] = s;
        }
        float mx = l[0];
#pragma unroll
        for (int e = 1; e < NEXP; e++) mx = fmaxf(mx, l[e]);
        float p[NEXP], sum = 0.f;
#pragma unroll
        for (int e = 0; e < NEXP; e++) { p[e] = expf(l[e] - mx); sum += p[e]; }
        float inv = 1.f / sum;
        bool used[NEXP];
#pragma unroll
        for (int e = 0; e < NEXP; e++) used[e] = false;
        for (int k = 0; k < TOPK; k++) {
            int best = 0; float bv = -1.f;
#pragma unroll
            for (int e = 0; e < NEXP; e++)
                if (!used[e] && p[e] > bv) { bv = p[e]; best = e; }
            used[best] = true;
            topi[t * TOPK + k] = best;
            topw[t * TOPK + k] = bv * inv;
            atomicAdd(&counts[best], 1);
        }
        gatev[t] = 1.f / (1.f + expf(-l[16]));
    }
}

__global__ void zero_counts_k(int* __restrict__ c) {
    if (threadIdx.x < NEXP) c[threadIdx.x] = 0;
}
__global__ void prefix_k(const int* __restrict__ c, int* __restrict__ off,
                         int* __restrict__ cur) {
    if (threadIdx.x == 0) {
        int s = 0;
        for (int e = 0; e < NEXP; e++) { off[e] = s; cur[e] = s; s += c[e]; }
    }
}
__global__ void scatter_k(const int* __restrict__ topi, int* __restrict__ cur,
                          int* __restrict__ btok, int* __restrict__ posmap, int TK) {
    int i = blockIdx.x * blockDim.x + threadIdx.x;
    if (i < TK) {
        int pos = atomicAdd(&cur[topi[i]], 1);
        btok[pos] = i >> 2;
        posmap[i] = pos;
    }
}

// ---------------------------------------------------------------------------
// Prep kernels
// ---------------------------------------------------------------------------
__global__ void cvtx_k(const float* __restrict__ x, u16* __restrict__ xh, size_t n) {
    size_t i = (size_t)blockIdx.x * blockDim.x + threadIdx.x;
    if (i < n) xh[i] = __half_as_ushort(__float2half_rn(x[i]));
}

// transpose [K,N] -> [N,K] fp16
__global__ void tsplit1_k(const float* __restrict__ in, u16* __restrict__ oh,
                          int K, int N) {
    __shared__ float t[32][33];
    size_t eo = (size_t)blockIdx.z * K * N;
    int n0 = blockIdx.x * 32, k0 = blockIdx.y * 32;
    for (int i = threadIdx.y; i < 32; i += 8)
        t[i][threadIdx.x] = in[eo + (size_t)(k0 + i) * N + n0 + threadIdx.x];
    __syncthreads();
    for (int i = threadIdx.y; i < 32; i += 8) {
        float v = t[threadIdx.x][i];
        oh[eo + (size_t)(n0 + i) * K + k0 + threadIdx.x] =
            __half_as_ushort(__float2half_rn(v));
    }
}

// transpose + interleave: source col n -> out row (n/8)*16 + sel*8 + n%8
__global__ void tinter_k(const float* __restrict__ in, u16* __restrict__ out,
                         int K, int N, int sel) {
    __shared__ float t[32][33];
    size_t eoi = (size_t)blockIdx.z * K * N;
    size_t eoo = (size_t)blockIdx.z * 2 * K * N;
    int n0 = blockIdx.x * 32, k0 = blockIdx.y * 32;
    for (int i = threadIdx.y; i < 32; i += 8)
        t[i][threadIdx.x] = in[eoi + (size_t)(k0 + i) * N + n0 + threadIdx.x];
    __syncthreads();
    for (int i = threadIdx.y; i < 32; i += 8) {
        float v = t[threadIdx.x][i];
        int n = n0 + i;
        int orow = ((n >> 3) << 4) + sel * 8 + (n & 7);
        out[eoo + (size_t)orow * K + k0 + threadIdx.x] =
            __half_as_ushort(__float2half_rn(v));
    }
}

// ---------------------------------------------------------------------------
// Single-term fp16 HMMA GEMM, 128x128 CTA tile, BK=64, 2 stages, 256 threads,
// 64x32 warp tiles. Inner body = round-14 fragment-prefetch pattern executed
// as two kk-pair halves; barriers amortized over 64 K-steps.
//   MODE 0: fused up-proj, B interleaved [w1|w3]; epilogue h=silu(g)*u -> Hh
//   MODE 1: down dense:  Fout[m*N+n] = gate[m]*acc
//   MODE 2: down routed: Fout[(off+m)*N+n] = acc  (A rows compact at off)
// ---------------------------------------------------------------------------
#define TILE_B 18432            // 128 rows * 144B (128B data + 16B pad)
#define STAGE_B2 (2 * TILE_B)   // A, B = 36,864
#define SMEM_G (2 * STAGE_B2)   // 73,728

template <int MODE, bool ROUTED>
__global__ void __launch_bounds__(256)
hmma_k(const u16* __restrict__ Ah, const u16* __restrict__ Bh,
       u16* __restrict__ Hh, float* __restrict__ Fout,
       const float* __restrict__ gate,
       const int* __restrict__ counts, const int* __restrict__ offsets,
       const int* __restrict__ btok, int M, int N, int Kd) {
    int Ne = M, off = 0;
    if (ROUTED) {
        int e = blockIdx.z;
        Ne = counts[e];
        off = offsets[e];
        Bh += (size_t)e * N * Kd;
    }
    int rowblock = blockIdx.y * 128;
    if (rowblock >= Ne) return;
    int colblock = blockIdx.x * 128;
    int Nlog = N >> 1;   // MODE 0 only

    extern __shared__ char dynsm[];
    u32 sbase = s2u(dynsm);

    int tid = threadIdx.x;
    int lane = tid & 31, wid = tid >> 5;
    int wm = wid >> 2, wn = wid & 3;   // warp tile: rows wm*64, cols wn*32

    // ---- loader: 8 x 16B cp.async per thread per chunk (2 tiles x 1024) ----
    const char* gptr[8];
    u32 soff[8];
#pragma unroll
    for (int j = 0; j < 8; j++) {
        int i = tid + 256 * j;
        int tile = i >> 10;         // 0 A, 1 B
        int idx = i & 1023;
        int row = idx >> 3, cc = idx & 7;
        soff[j] = tile * TILE_B + row * 144 + cc * 16;
        const u16* bp;
        if (tile == 0) {
            int m = rowblock + row;
            int mc = (m < Ne) ? m : (Ne - 1);
            size_t gr;
            if (ROUTED) gr = (MODE == 0) ? (size_t)btok[off + mc] : (size_t)(off + mc);
            else gr = (size_t)mc;
            bp = Ah + gr * Kd;
        } else {
            bp = Bh + (size_t)(colblock + row) * Kd;
        }
        gptr[j] = (const char*)bp + cc * 16;
    }

    const int NC = Kd >> 6;  // BK = 64

    auto load_chunk = [&](int c, int s) {
        u32 stg = sbase + s * STAGE_B2;
        int kb = c * 128;   // 64 fp16 = 128 bytes
#pragma unroll
        for (int j = 0; j < 8; j++) cp16(stg + soff[j], gptr[j] + kb);
        asm volatile("cp.async.commit_group;" ::: "memory");
    };

    float acc[4][4][4];
#pragma unroll
    for (int a = 0; a < 4; a++)
#pragma unroll
        for (int b = 0; b < 4; b++)
#pragma unroll
            for (int d = 0; d < 4; d++) acc[a][b][d] = 0.f;

    u32 aoff = (u32)(((lane & 7) + ((lane >> 3) & 1) * 8) * 144 + ((lane >> 4) & 1) * 16);
    u32 boff = (u32)(((lane & 7) + ((lane >> 4) & 1) * 8) * 144 + ((lane >> 3) & 1) * 16);

    load_chunk(0, 0);
    load_chunk(1, 1);

    for (int c = 0; c < NC; c++) {
        int s = c & 1;
        if (c + 1 < NC) asm volatile("cp.async.wait_group 1;" ::: "memory");
        else            asm volatile("cp.async.wait_group 0;" ::: "memory");
        __syncthreads();

        u32 ab = sbase + s * STAGE_B2;

        // 64 K-steps = 4 kk of 16; process as two kk-pair halves with the
        // round-14 fragment-prefetch pattern (identical register profile).
#pragma unroll
        for (int half = 0; half < 2; half++) {
            u32 ah[2][4][4], bh[2][4][2];
#pragma unroll
            for (int k2 = 0; k2 < 2; k2++) {
                int kk = half * 2 + k2;
#pragma unroll
                for (int mt = 0; mt < 4; mt++) {
                    u32 addr = ab + (u32)((wm * 64 + mt * 16) * 144) + aoff + kk * 32;
                    ldsm_x4(addr, ah[k2][mt][0], ah[k2][mt][1], ah[k2][mt][2], ah[k2][mt][3]);
                }
                u32 bb = ab + TILE_B + (u32)(wn * 32 * 144) + boff + kk * 32;
                ldsm_x4(bb,            bh[k2][0][0], bh[k2][0][1], bh[k2][1][0], bh[k2][1][1]);
                ldsm_x4(bb + 16 * 144, bh[k2][2][0], bh[k2][2][1], bh[k2][3][0], bh[k2][3][1]);
            }
#pragma unroll
            for (int k2 = 0; k2 < 2; k2++)
#pragma unroll
                for (int mt = 0; mt < 4; mt++)
#pragma unroll
                    for (int nt = 0; nt < 4; nt++)
                        mma16816(acc[mt][nt], ah[k2][mt][0], ah[k2][mt][1],
                                 ah[k2][mt][2], ah[k2][mt][3],
                                 bh[k2][nt][0], bh[k2][nt][1]);
        }

        __syncthreads();
        if (c + 2 < NC) load_chunk(c + 2, s);
    }

    // ---- epilogue ----
    int g = lane >> 2, q = lane & 3;
#pragma unroll
    for (int mt = 0; mt < 4; mt++) {
#pragma unroll
        for (int h2 = 0; h2 < 2; h2++) {
            int m = rowblock + wm * 64 + mt * 16 + g + 8 * h2;
            if (m >= Ne) continue;
            size_t orow = (size_t)((ROUTED ? off : 0) + m);
            if (MODE == 0) {
#pragma unroll
                for (int j = 0; j < 2; j++) {
                    float g0 = acc[mt][2 * j][2 * h2 + 0];
                    float g1 = acc[mt][2 * j][2 * h2 + 1];
                    float u0 = acc[mt][2 * j + 1][2 * h2 + 0];
                    float u1 = acc[mt][2 * j + 1][2 * h2 + 1];
                    float h0 = (g0 / (1.f + expf(-g0))) * u0;
                    float h1 = (g1 / (1.f + expf(-g1))) * u1;
                    int nlog = (colblock >> 1) + wn * 16 + j * 8 + 2 * q;
                    *(u32*)&Hh[orow * Nlog + nlog] =
                        (u32)__half_as_ushort(__float2half_rn(h0)) |
                        ((u32)__half_as_ushort(__float2half_rn(h1)) << 16);
                }
            } else {
                float gsc = (MODE == 1) ? gate[m] : 1.f;
#pragma unroll
                for (int nt = 0; nt < 4; nt++) {
                    int n = colblock + wn * 32 + nt * 8 + 2 * q;
                    float v0 = gsc * acc[mt][nt][2 * h2 + 0];
                    float v1 = gsc * acc[mt][nt][2 * h2 + 1];
                    *(float2*)&Fout[orow * N + n] = make_float2(v0, v1);
                }
            }
        }
    }
}

// ---------------------------------------------------------------------------
// Combine: out[t,:] += sum_k topw[t,k] * dtmp[posmap[t,k],:]
// ---------------------------------------------------------------------------
__global__ void combine_k(float* __restrict__ out, const float* __restrict__ dtmp,
                          const int* __restrict__ posmap, const float* __restrict__ topw,
                          int T) {
    int idx = blockIdx.x * blockDim.x + threadIdx.x;
    int HV = HDIM / 4;
    if (idx >= T * HV) return;
    int t = idx / HV, hv = idx % HV;
    float4 o = ((const float4*)out)[idx];
#pragma unroll
    for (int k = 0; k < TOPK; k++) {
        int p = posmap[t * TOPK + k];
        float w = topw[t * TOPK + k];
        float4 d = ((const float4*)dtmp)[(size_t)p * HV + hv];
        o.x += w * d.x; o.y += w * d.y; o.z += w * d.z; o.w += w * d.w;
    }
    ((float4*)out)[idx] = o;
}

// ---------------------------------------------------------------------------
// kernel_launch
// ---------------------------------------------------------------------------
extern "C" void kernel_launch(void* const* d_in, const int* in_sizes, int n_in,
                              void* d_out, int out_size) {
    const float* x   = (const float*)d_in[0];
    const float* gw  = (const float*)d_in[1];
    const float* w1  = (const float*)d_in[2];
    const float* w3  = (const float*)d_in[3];
    const float* w2  = (const float*)d_in[4];
    const float* sw1 = (const float*)d_in[5];
    const float* sw3 = (const float*)d_in[6];
    const float* sw2 = (const float*)d_in[7];
    const float* sgw = (const float*)d_in[8];
    float* out = (float*)d_out;

    const int T = in_sizes[0] / HDIM;   // 8192
    const int TK = T * TOPK;

    u16 *wu, *w2h, *su, *s2h, *xh, *hh;
    float *dtmp, *topw, *gatev;
    int *topi, *counts, *offsets, *cursor, *btok, *posmap;
    cudaGetSymbolAddress((void**)&wu, g_wu);
    cudaGetSymbolAddress((void**)&w2h, g_w2h);
    cudaGetSymbolAddress((void**)&su, g_su);
    cudaGetSymbolAddress((void**)&s2h, g_s2h);
    cudaGetSymbolAddress((void**)&xh, g_xh);
    cudaGetSymbolAddress((void**)&hh, g_hh);
    cudaGetSymbolAddress((void**)&dtmp, g_dtmp);
    cudaGetSymbolAddress((void**)&topi, g_topi);
    cudaGetSymbolAddress((void**)&topw, g_topw);
    cudaGetSymbolAddress((void**)&gatev, g_gate);
    cudaGetSymbolAddress((void**)&counts, g_counts);
    cudaGetSymbolAddress((void**)&offsets, g_offsets);
    cudaGetSymbolAddress((void**)&cursor, g_cursor);
    cudaGetSymbolAddress((void**)&btok, g_btok);
    cudaGetSymbolAddress((void**)&posmap, g_posmap);

    cudaFuncSetAttribute(hmma_k<0, false>, cudaFuncAttributeMaxDynamicSharedMemorySize, SMEM_G);
    cudaFuncSetAttribute(hmma_k<0, true>,  cudaFuncAttributeMaxDynamicSharedMemorySize, SMEM_G);
    cudaFuncSetAttribute(hmma_k<1, false>, cudaFuncAttributeMaxDynamicSharedMemorySize, SMEM_G);
    cudaFuncSetAttribute(hmma_k<2, true>,  cudaFuncAttributeMaxDynamicSharedMemorySize, SMEM_G);

    // ---- routing ----
    zero_counts_k<<<1, 32>>>(counts);
    router_k<<<T, 256>>>(x, gw, sgw, topi, topw, gatev, counts);
    prefix_k<<<1, 32>>>(counts, offsets, cursor);
    scatter_k<<<(TK + 255) / 256, 256>>>(topi, cursor, btok, posmap, TK);

    // ---- prep ----
    {
        size_t n = (size_t)T * HDIM;
        cvtx_k<<<(int)((n + 255) / 256), 256>>>(x, xh, n);
        dim3 b(32, 8);
        tinter_k<<<dim3(IDIM / 32, HDIM / 32, NEXP), b>>>(w1, wu, HDIM, IDIM, 0);
        tinter_k<<<dim3(IDIM / 32, HDIM / 32, NEXP), b>>>(w3, wu, HDIM, IDIM, 1);
        tsplit1_k<<<dim3(HDIM / 32, IDIM / 32, NEXP), b>>>(w2, w2h, IDIM, HDIM);
        tinter_k<<<dim3(ISDIM / 32, HDIM / 32, 1), b>>>(sw1, su, HDIM, ISDIM, 0);
        tinter_k<<<dim3(ISDIM / 32, HDIM / 32, 1), b>>>(sw3, su, HDIM, ISDIM, 1);
        tsplit1_k<<<dim3(HDIM / 32, ISDIM / 32, 1), b>>>(sw2, s2h, ISDIM, HDIM);
    }

    // ---- shared expert ----
    hmma_k<0, false><<<dim3(2 * ISDIM / 128, T / 128), 256, SMEM_G>>>(
        xh, su, hh, nullptr, nullptr, nullptr, nullptr, nullptr,
        T, 2 * ISDIM, HDIM);
    hmma_k<1, false><<<dim3(HDIM / 128, T / 128), 256, SMEM_G>>>(
        hh, s2h, nullptr, out, gatev, nullptr, nullptr, nullptr,
        T, HDIM, ISDIM);

    // ---- routed experts ----
    hmma_k<0, true><<<dim3(2 * IDIM / 128, TK / 128, NEXP), 256, SMEM_G>>>(
        xh, wu, hh, nullptr, nullptr, counts, offsets, btok,
        TK, 2 * IDIM, HDIM);
    hmma_k<2, true><<<dim3(HDIM / 128, TK / 128, NEXP), 256, SMEM_G>>>(
        hh, w2h, nullptr, dtmp, nullptr, counts, offsets, nullptr,
        TK, HDIM, IDIM);

    // ---- combine ----
    combine_k<<<(T * (HDIM / 4) + 255) / 256, 256>>>(out, dtmp, posmap, topw, T);
}